// round 13
// baseline (speedup 1.0000x reference)
#include <cuda_runtime.h>
#include <cstdint>

// Fixed shapes: pred/target = [4, 8192, 3] fp32
#define NB        4
#define NPTS      8192
#define THREADS   128
#define OCC       8
#define IPT       8                      // pred points per lane
#define JT        32                     // targets per warp-tile
#define TILES     256                    // j-tiles per queue (256*32 = 8192)
#define NQ        128                    // (b, ich, quarter) queues: 4*8*4
#define WPQ       37                     // warps per queue
#define NWARPS    (NQ * WPQ)             // 4736
#define GRID      (NWARPS / 4)           // 1184 CTAs = 148 SMs * 8
#define INF_BITS  0x7f800000

// Global mins as int bits (values >= 0 -> IEEE order == int order).
__device__ int          g_rmin[NB * NPTS];
__device__ int          g_cmin[NB * NPTS];
__device__ unsigned int g_next[NQ];      // per-queue tile counters
__device__ unsigned int g_done;

__global__ void chamfer_init_kernel() {
    int idx = blockIdx.x * blockDim.x + threadIdx.x;   // 8192 threads
    int4 v = make_int4(INF_BITS, INF_BITS, INF_BITS, INF_BITS);
    reinterpret_cast<int4*>(g_rmin)[idx] = v;
    reinterpret_cast<int4*>(g_cmin)[idx] = v;
    if (idx < NQ) g_next[idx] = 0u;
    if (idx == 0) g_done = 0u;
}

// Warp-autonomous persistent symmetric cross kernel. Each (i,j) computed once:
//   s = h_q - p.q  (3 FFMA, negated-p modifiers, q.w = +h_q)
//   rows: min(s), h_p folded in at flush; cols: t = h_p + s, 8-tree,
//   systolic SHFL ride (1 SHFL per 256 pairs), flushed by REDG.MIN per tile.
__global__ void __launch_bounds__(THREADS, OCC)
chamfer_cross_kernel(const float* __restrict__ pred, const float* __restrict__ tgt,
                     float* __restrict__ out) {
    // Per-warp duplicated tile: sq[w][m] = q[tile*32 + (m & 31)], m in [0,63)
    __shared__ float4 sq[4][64];

    const int tid   = threadIdx.x;
    const int w     = tid >> 5;
    const int lane  = tid & 31;
    const int gwarp = blockIdx.x * 4 + w;
    const int qid   = gwarp / WPQ;          // 0..127
    const int combo = qid >> 2;             // 0..31
    const int quart = qid & 3;
    const int b     = combo >> 3;
    const int ich   = combo & 7;

    const float* P = pred + (size_t)b * NPTS * 3;
    const float* Q = tgt  + (size_t)b * NPTS * 3;
    int* grow = &g_rmin[b * NPTS];
    int* gcol = &g_cmin[b * NPTS];

    // Register-resident pred points (fixed for this warp's whole lifetime).
    const int ib = ich * 1024 + quart * 256 + lane * IPT;
    float px[IPT], py[IPT], pz[IPT], hp[IPT], smin[IPT];
#pragma unroll
    for (int k = 0; k < IPT; k++) {
        float x = P[3 * (ib + k) + 0];
        float y = P[3 * (ib + k) + 1];
        float z = P[3 * (ib + k) + 2];
        px[k] = x; py[k] = y; pz[k] = z;
        hp[k] = 0.5f * fmaf(x, x, fmaf(y, y, z * z));
        smin[k] = __int_as_float(INF_BITS);
    }

    // Two-ahead tile pipeline: t_cur staged via qreg, t_nx drawn.
    unsigned int t_cur = 0xffffffffu, t_nx = 0xffffffffu;
    if (lane == 0) t_cur = atomicAdd(&g_next[qid], 1u);
    t_cur = __shfl_sync(0xffffffffu, t_cur, 0);
    float4 qreg = make_float4(0.f, 0.f, 0.f, 0.f);
    if (t_cur < TILES) {
        int gj = t_cur * JT + lane;
        float x = Q[3 * gj + 0], y = Q[3 * gj + 1], z = Q[3 * gj + 2];
        qreg = make_float4(x, y, z, 0.5f * fmaf(x, x, fmaf(y, y, z * z)));
    }
    if (lane == 0) t_nx = atomicAdd(&g_next[qid], 1u);

    while (t_cur < TILES) {
        // Stage current tile (duplicated halves for wrap-free systolic reads).
        sq[w][lane] = qreg;
        if (lane < 31) sq[w][32 + lane] = qreg;

        // Broadcast next tile id; issue its loads (latency hidden by compute).
        unsigned int nt = __shfl_sync(0xffffffffu, t_nx, 0);
        if (nt < TILES) {
            int gj = nt * JT + lane;
            float x = Q[3 * gj + 0], y = Q[3 * gj + 1], z = Q[3 * gj + 2];
            qreg = make_float4(x, y, z, 0.5f * fmaf(x, x, fmaf(y, y, z * z)));
        }
        if (lane == 0) t_nx = atomicAdd(&g_next[qid], 1u);   // draw 2-ahead
        __syncwarp();

        // 32 systolic steps; cm rides one SHFL per step, lands on home lane.
        const float4* qp = &sq[w][lane];
        float cm = __int_as_float(INF_BITS);
#pragma unroll 8
        for (int n = 0; n < 32; n++) {
            float4 q = qp[n];                        // LDS.128, ptr bump only
            float tm;
#pragma unroll
            for (int k = 0; k < IPT; k += 2) {
                float s0 = fmaf(-pz[k],     q.z, fmaf(-py[k],     q.y, fmaf(-px[k],     q.x, q.w)));
                float s1 = fmaf(-pz[k + 1], q.z, fmaf(-py[k + 1], q.y, fmaf(-px[k + 1], q.x, q.w)));
                smin[k]     = fminf(smin[k],     s0);
                smin[k + 1] = fminf(smin[k + 1], s1);
                float t0 = fmaf(s0, 1.0f, hp[k]);    // t = hp + s (FFMA-imm)
                float t1 = fmaf(s1, 1.0f, hp[k + 1]);
                float tp = fminf(t0, t1);
                tm = (k == 0) ? tp : fminf(tm, tp);
            }
            cm = fminf(cm, tm);
            cm = __shfl_sync(0xffffffffu, cm, lane + 1);
        }

        // Col flush for home j, straight from register.
        atomicMin(&gcol[t_cur * JT + lane], __float_as_int(cm));
        __syncwarp();                                // before next STS overwrite
        t_cur = nt;
    }

    // Row flush once per warp (add hp back here).
#pragma unroll
    for (int k = 0; k < IPT; k++)
        atomicMin(&grow[ib + k], __float_as_int(hp[k] + smin[k]));

    // Last finishing warp reduces everything to the scalar output.
    __threadfence();
    unsigned int done = 0;
    if (lane == 0) done = atomicAdd(&g_done, 1u);
    done = __shfl_sync(0xffffffffu, done, 0);
    if (done != NWARPS - 1) return;
    __threadfence();

    const int4* r4 = reinterpret_cast<const int4*>(g_rmin);
    const int4* c4 = reinterpret_cast<const int4*>(g_cmin);
    float sum = 0.0f;
    for (int i = lane; i < (NB * NPTS) / 4; i += 32) {
        int4 a = r4[i], c = c4[i];
        sum += __int_as_float(a.x) + __int_as_float(a.y) +
               __int_as_float(a.z) + __int_as_float(a.w) +
               __int_as_float(c.x) + __int_as_float(c.y) +
               __int_as_float(c.z) + __int_as_float(c.w);
    }
#pragma unroll
    for (int o = 16; o; o >>= 1)
        sum += __shfl_xor_sync(0xffffffffu, sum, o);
    // values are dist^2/2 -> x2; mean over NB batches and NPTS points.
    if (lane == 0)
        *out = sum * (2.0f / ((float)NB * (float)NPTS));
}

extern "C" void kernel_launch(void* const* d_in, const int* in_sizes, int n_in,
                              void* d_out, int out_size) {
    const float* pred = (const float*)d_in[0];
    const float* tgt  = (const float*)d_in[1];
    float* out = (float*)d_out;
    (void)in_sizes; (void)n_in; (void)out_size;

    chamfer_init_kernel<<<32, 256>>>();
    chamfer_cross_kernel<<<GRID, THREADS>>>(pred, tgt, out);
}